// round 5
// baseline (speedup 1.0000x reference)
#include <cuda_runtime.h>
#include <cuda_fp16.h>
#include <cuda_bf16.h>
#include <mma.h>
#include <math.h>
#include <cstdint>

using namespace nvcuda;

#define BATCH   2
#define SEQ     2048
#define DMODEL  2048
#define HEADS   16
#define DKH     128
#define MROWS   (BATCH*SEQ)

// ---------------- scratch (__device__ globals; allocation-free rule) -------
__device__ float  g_Q [BATCH*HEADS*SEQ*DKH];
__device__ float  g_K [BATCH*HEADS*SEQ*DKH];
__device__ float  g_V [BATCH*HEADS*SEQ*DKH];
__device__ __half g_Qh[BATCH*HEADS*SEQ*DKH];
__device__ __half g_Kh[BATCH*HEADS*SEQ*DKH];
__device__ __half g_Vh[BATCH*HEADS*SEQ*DKH];
__device__ __half g_xh [MROWS*DMODEL];
__device__ __half g_wqh[DMODEL*DMODEL];
__device__ __half g_wkh[DMODEL*DMODEL];
__device__ __half g_wvh[DMODEL*DMODEL];
__device__ __half g_woh[DMODEL*DMODEL];
__device__ __half g_aoh[MROWS*DMODEL];

// ---------------------------------------------------------------------------
__global__ void f32_to_f16(const float* __restrict__ in, __half* __restrict__ out, int n4)
{
    int i = blockIdx.x * blockDim.x + threadIdx.x;
    if (i >= n4) return;
    float4 v = *(const float4*)(in + (size_t)i*4);
    *(__half2*)(out + (size_t)i*4)     = __floats2half2_rn(v.x, v.y);
    *(__half2*)(out + (size_t)i*4 + 2) = __floats2half2_rn(v.z, v.w);
}

// 4 weight matrices in one launch (blockIdx.y selects)
__global__ void w_to_f16(const float* __restrict__ w0, const float* __restrict__ w1,
                         const float* __restrict__ w2, const float* __restrict__ w3,
                         __half* __restrict__ o0, __half* __restrict__ o1,
                         __half* __restrict__ o2, __half* __restrict__ o3, int n4)
{
    const float* in;
    __half* out;
    switch (blockIdx.y) {
        case 0: in = w0; out = o0; break;
        case 1: in = w1; out = o1; break;
        case 2: in = w2; out = o2; break;
        default: in = w3; out = o3; break;
    }
    int i = blockIdx.x * blockDim.x + threadIdx.x;
    if (i >= n4) return;
    float4 v = *(const float4*)(in + (size_t)i*4);
    *(__half2*)(out + (size_t)i*4)     = __floats2half2_rn(v.x, v.y);
    *(__half2*)(out + (size_t)i*4 + 2) = __floats2half2_rn(v.z, v.w);
}

// ---------------------------------------------------------------------------
__device__ __forceinline__ void cp_async16(void* smem, const void* gmem)
{
    unsigned int s = (unsigned int)__cvta_generic_to_shared(smem);
    asm volatile("cp.async.cg.shared.global [%0], [%1], 16;\n" :: "r"(s), "l"(gmem));
}
__device__ __forceinline__ void cp_commit() { asm volatile("cp.async.commit_group;\n"); }
template<int N> __device__ __forceinline__ void cp_wait() { asm volatile("cp.async.wait_group %0;\n" :: "n"(N)); }

__device__ __forceinline__ unsigned int smaddr(const void* p)
{ return (unsigned int)__cvta_generic_to_shared(p); }

__device__ __forceinline__ void ldsm4(uint32_t* r, unsigned int a)
{
    asm volatile("ldmatrix.sync.aligned.m8n8.x4.shared.b16 {%0,%1,%2,%3}, [%4];"
                 : "=r"(r[0]), "=r"(r[1]), "=r"(r[2]), "=r"(r[3]) : "r"(a));
}
__device__ __forceinline__ void ldsm4t(uint32_t* r, unsigned int a)
{
    asm volatile("ldmatrix.sync.aligned.m8n8.x4.trans.shared.b16 {%0,%1,%2,%3}, [%4];"
                 : "=r"(r[0]), "=r"(r[1]), "=r"(r[2]), "=r"(r[3]) : "r"(a));
}
__device__ __forceinline__ void mma16816(float* d, const uint32_t* a, const uint32_t* b)
{
    asm volatile("mma.sync.aligned.m16n8k16.row.col.f32.f16.f16.f32 "
                 "{%0,%1,%2,%3},{%4,%5,%6,%7},{%8,%9},{%0,%1,%2,%3};"
                 : "+f"(d[0]), "+f"(d[1]), "+f"(d[2]), "+f"(d[3])
                 : "r"(a[0]), "r"(a[1]), "r"(a[2]), "r"(a[3]), "r"(b[0]), "r"(b[1]));
}

// ---------------------------------------------------------------------------
// fp16 WMMA GEMM, 256x128 CTA tile, 64x64 warp tile, 4-stage cp.async.
//   C[m,n] = sum_k A[m,k] * W[n,k]
// QKV=true: blockIdx.z selects (W,C); output scattered headwise.
// ---------------------------------------------------------------------------
#define GSTAGES 4
#define GBK     32
#define GAP     40
#define GBM     256
#define GBN     128
#define ATILE_HALVES (GBM*GAP)
#define BTILE_HALVES (GBN*GAP)
#define GSTAGE_HALVES (ATILE_HALVES + BTILE_HALVES)
#define GEMM_SMEM_BYTES (GSTAGES*GSTAGE_HALVES*(int)sizeof(__half))

template<bool QKV>
__global__ __launch_bounds__(256, 1)
void gemm_f16(const __half* __restrict__ A,
              const __half* __restrict__ W0, const __half* __restrict__ W1, const __half* __restrict__ W2,
              float* __restrict__ C0, float* __restrict__ C1, float* __restrict__ C2)
{
    extern __shared__ __half sm_h[];

    const __half* W = W0;
    float* C = C0;
    if (QKV) {
        if (blockIdx.z == 1) { W = W1; C = C1; }
        else if (blockIdx.z == 2) { W = W2; C = C2; }
    }

    const int m0  = blockIdx.y * GBM;
    const int n0  = blockIdx.x * GBN;
    const int tid = threadIdx.x;
    const int wid = tid >> 5;
    const int wm  = wid & 3;          // 4 warp rows  (4*64 = 256)
    const int wn  = wid >> 2;         // 2 warp cols  (2*64 = 128)

    wmma::fragment<wmma::accumulator,16,16,16,float> c[4][4];
#pragma unroll
    for (int i = 0; i < 4; i++)
#pragma unroll
        for (int j = 0; j < 4; j++)
            wmma::fill_fragment(c[i][j], 0.0f);

    const int NT = 2048 / GBK;

    auto load_stage = [&](int kt) {
        __half* sA = sm_h + (kt & (GSTAGES-1)) * GSTAGE_HALVES;
        __half* sB = sA + ATILE_HALVES;
        const int kbase = kt * GBK;
#pragma unroll
        for (int it = 0; it < 4; it++) {       // 1024 chunks for A (256 rows x 4)
            int idx = it*256 + tid;
            int row = idx >> 2, cc = idx & 3;
            cp_async16(&sA[row*GAP + cc*8], A + (size_t)(m0+row)*2048 + kbase + cc*8);
        }
#pragma unroll
        for (int it = 0; it < 2; it++) {       // 512 chunks for B (128 rows x 4)
            int idx = it*256 + tid;
            int row = idx >> 2, cc = idx & 3;
            cp_async16(&sB[row*GAP + cc*8], W + (size_t)(n0+row)*2048 + kbase + cc*8);
        }
    };

#pragma unroll
    for (int s = 0; s < GSTAGES-1; s++) { load_stage(s); cp_commit(); }

    for (int kt = 0; kt < NT; kt++) {
        cp_wait<GSTAGES-2>();
        __syncthreads();
        if (kt + GSTAGES-1 < NT) load_stage(kt + GSTAGES-1);
        cp_commit();

        __half* sA = sm_h + (kt & (GSTAGES-1)) * GSTAGE_HALVES;
        __half* sB = sA + ATILE_HALVES;
#pragma unroll
        for (int ks = 0; ks < 2; ks++) {
            wmma::fragment<wmma::matrix_a,16,16,16,__half,wmma::row_major> a[4];
            wmma::fragment<wmma::matrix_b,16,16,16,__half,wmma::col_major> b[4];
#pragma unroll
            for (int i = 0; i < 4; i++)
                wmma::load_matrix_sync(a[i], &sA[(wm*64 + i*16)*GAP + ks*16], GAP);
#pragma unroll
            for (int j = 0; j < 4; j++)
                wmma::load_matrix_sync(b[j], &sB[(wn*64 + j*16)*GAP + ks*16], GAP);
#pragma unroll
            for (int i = 0; i < 4; i++)
#pragma unroll
                for (int j = 0; j < 4; j++)
                    wmma::mma_sync(c[i][j], a[i], b[j], c[i][j]);
        }
    }

    if (QKV) {
        const int b  = m0 / SEQ;
        const int s0 = m0 % SEQ;
        const int h  = blockIdx.x;
        float* base = C + ((size_t)(b*HEADS + h)*SEQ + s0) * DKH;
#pragma unroll
        for (int i = 0; i < 4; i++)
#pragma unroll
            for (int j = 0; j < 4; j++)
                wmma::store_matrix_sync(base + (size_t)(wm*64 + i*16)*DKH + wn*64 + j*16,
                                        c[i][j], DKH, wmma::mem_row_major);
    } else {
        float* base = C + (size_t)m0*DMODEL + n0;
#pragma unroll
        for (int i = 0; i < 4; i++)
#pragma unroll
            for (int j = 0; j < 4; j++)
                wmma::store_matrix_sync(base + (size_t)(wm*64 + i*16)*DMODEL + wn*64 + j*16,
                                        c[i][j], DMODEL, wmma::mem_row_major);
    }
}

// ---------------------------------------------------------------------------
// RoPE fp32 -> fp16 (scale folded in for Q). positions == s by construction.
// ---------------------------------------------------------------------------
__global__ void rope_to_f16(const float* __restrict__ X, __half* __restrict__ Xh, float scale)
{
    int idx = blockIdx.x * blockDim.x + threadIdx.x;
    if (idx >= BATCH*HEADS*SEQ*(DKH/2)) return;
    int dd = idx & 63;
    int s  = (idx >> 6) & (SEQ - 1);
    float freq = exp2f(-13.287712379549449f * ((float)(2*dd) * (1.0f/128.0f)));
    float ang  = (float)s * freq;
    float sn, cs;
    sincosf(ang, &sn, &cs);
    const float* p = X + (size_t)idx * 2;
    float x1 = p[0], x2 = p[1];
    float y1 = (x1*cs - x2*sn) * scale;
    float y2 = (x1*sn + x2*cs) * scale;
    *(__half2*)(Xh + (size_t)idx*2) = __floats2half2_rn(y1, y2);
}

// ---------------------------------------------------------------------------
// FA2-style fp16 flash attention (causal) — unchanged from R4 (known good).
// ---------------------------------------------------------------------------
#define BR 128
#define BC 64
#define DPAD 136
#define KV_STAGE_HALVES (2*BC*DPAD)
#define FL_SMEM_BYTES (2*KV_STAGE_HALVES*(int)sizeof(__half))

__global__ __launch_bounds__(256, 1)
void flash16(const __half* __restrict__ Q, const __half* __restrict__ K,
             const __half* __restrict__ V, __half* __restrict__ AO)
{
    extern __shared__ __half smf[];
    __half* buf0 = smf;
    __half* buf1 = smf + KV_STAGE_HALVES;

    const int qt  = (gridDim.x - 1) - blockIdx.x;
    const int bh  = blockIdx.y;
    const int q0  = qt * BR;
    const int tid = threadIdx.x;
    const int lane = tid & 31;
    const int wid  = tid >> 5;
    const int g    = lane >> 2;
    const int t4   = lane & 3;
    const int l8   = lane & 7;

    const __half* Qg = Q + ((size_t)bh * SEQ + q0) * DKH;
    for (int i = tid; i < BR*16; i += 256) {
        int r = i >> 4, c = i & 15;
        cp_async16(&buf1[r*DPAD + c*8], Qg + (size_t)r*DKH + c*8);
    }
    cp_commit();
    cp_wait<0>();
    __syncthreads();

    uint32_t qf[8][4];
    {
        int row  = wid*16 + ((lane >> 3) & 1)*8 + l8;
        int koff = (lane >> 4) * 8;
#pragma unroll
        for (int ks = 0; ks < 8; ks++)
            ldsm4(qf[ks], smaddr(&buf1[row*DPAD + ks*16 + koff]));
    }
    __syncthreads();

    float o[16][4];
#pragma unroll
    for (int i = 0; i < 16; i++)
#pragma unroll
        for (int j = 0; j < 4; j++) o[i][j] = 0.0f;
    float m1 = -1e30f, m2 = -1e30f, l1 = 0.0f, l2 = 0.0f;

    auto loadKV = [&](int t, int stage) {
        const __half* Kg = K + ((size_t)bh * SEQ + t*BC) * DKH;
        const __half* Vg = V + ((size_t)bh * SEQ + t*BC) * DKH;
        __half* s  = stage ? buf1 : buf0;
        __half* sv = s + BC*DPAD;
#pragma unroll
        for (int it = 0; it < 4; it++) {
            int i = it*256 + tid;
            int r = i >> 4, c = i & 15;
            cp_async16(&s[r*DPAD + c*8],  Kg + (size_t)r*DKH + c*8);
        }
#pragma unroll
        for (int it = 0; it < 4; it++) {
            int i = it*256 + tid;
            int r = i >> 4, c = i & 15;
            cp_async16(&sv[r*DPAD + c*8], Vg + (size_t)r*DKH + c*8);
        }
    };

    const int nt = 2*qt + 2;
    loadKV(0, 0);
    cp_commit();

    for (int t = 0; t < nt; t++) {
        if (t + 1 < nt) { loadKV(t+1, (t+1) & 1); cp_commit(); cp_wait<1>(); }
        else            { cp_wait<0>(); }
        __syncthreads();

        __half* sk = (t & 1) ? buf1 : buf0;
        __half* sv = sk + BC*DPAD;

        float s[8][4];
#pragma unroll
        for (int i = 0; i < 8; i++)
#pragma unroll
            for (int j = 0; j < 4; j++) s[i][j] = 0.0f;

#pragma unroll
        for (int ks = 0; ks < 8; ks++) {
#pragma unroll
            for (int nb2 = 0; nb2 < 4; nb2++) {
                uint32_t kf[4];
                int row  = nb2*16 + ((lane >> 4) & 1)*8 + l8;
                int koff = ks*16 + ((lane >> 3) & 1)*8;
                ldsm4(kf, smaddr(&sk[row*DPAD + koff]));
                mma16816(s[nb2*2],     qf[ks], kf);
                mma16816(s[nb2*2 + 1], qf[ks], kf + 2);
            }
        }

        if (t >= 2*qt) {
            int row1 = q0 + wid*16 + g;
            int row2 = row1 + 8;
            int cb   = t*BC + t4*2;
#pragma unroll
            for (int nb = 0; nb < 8; nb++) {
                int c0 = cb + nb*8, c1 = c0 + 1;
                if (c0 > row1) s[nb][0] = -1e30f;
                if (c1 > row1) s[nb][1] = -1e30f;
                if (c0 > row2) s[nb][2] = -1e30f;
                if (c1 > row2) s[nb][3] = -1e30f;
            }
        }

        float mx1 = -1e30f, mx2 = -1e30f;
#pragma unroll
        for (int nb = 0; nb < 8; nb++) {
            mx1 = fmaxf(mx1, fmaxf(s[nb][0], s[nb][1]));
            mx2 = fmaxf(mx2, fmaxf(s[nb][2], s[nb][3]));
        }
        mx1 = fmaxf(mx1, __shfl_xor_sync(0xffffffffu, mx1, 1));
        mx1 = fmaxf(mx1, __shfl_xor_sync(0xffffffffu, mx1, 2));
        mx2 = fmaxf(mx2, __shfl_xor_sync(0xffffffffu, mx2, 1));
        mx2 = fmaxf(mx2, __shfl_xor_sync(0xffffffffu, mx2, 2));

        float m1n = fmaxf(m1, mx1);
        float m2n = fmaxf(m2, mx2);
        float a1  = __expf(m1 - m1n);
        float a2  = __expf(m2 - m2n);

        uint32_t pf[4][4];
        float ls1 = 0.0f, ls2 = 0.0f;
#pragma unroll
        for (int nb = 0; nb < 8; nb++) {
            float p0 = __expf(s[nb][0] - m1n);
            float p1 = __expf(s[nb][1] - m1n);
            float p2 = __expf(s[nb][2] - m2n);
            float p3 = __expf(s[nb][3] - m2n);
            ls1 += p0 + p1;
            ls2 += p2 + p3;
            __half2 h01 = __floats2half2_rn(p0, p1);
            __half2 h23 = __floats2half2_rn(p2, p3);
            int ks = nb >> 1;
            if ((nb & 1) == 0) {
                pf[ks][0] = *(uint32_t*)&h01;
                pf[ks][1] = *(uint32_t*)&h23;
            } else {
                pf[ks][2] = *(uint32_t*)&h01;
                pf[ks][3] = *(uint32_t*)&h23;
            }
        }
        ls1 += __shfl_xor_sync(0xffffffffu, ls1, 1);
        ls1 += __shfl_xor_sync(0xffffffffu, ls1, 2);
        ls2 += __shfl_xor_sync(0xffffffffu, ls2, 1);
        ls2 += __shfl_xor_sync(0xffffffffu, ls2, 2);

        l1 = l1*a1 + ls1;
        l2 = l2*a2 + ls2;
        m1 = m1n; m2 = m2n;

#pragma unroll
        for (int nb2 = 0; nb2 < 16; nb2++) {
            o[nb2][0] *= a1; o[nb2][1] *= a1;
            o[nb2][2] *= a2; o[nb2][3] *= a2;
        }

#pragma unroll
        for (int ks = 0; ks < 4; ks++) {
#pragma unroll
            for (int nbp = 0; nbp < 8; nbp++) {
                uint32_t vf[4];
                int vrow = ks*16 + ((lane >> 3) & 1)*8 + l8;
                int vcol = nbp*16 + (lane >> 4)*8;
                ldsm4t(vf, smaddr(&sv[vrow*DPAD + vcol]));
                mma16816(o[nbp*2],     pf[ks], vf);
                mma16816(o[nbp*2 + 1], pf[ks], vf + 2);
            }
        }

        __syncthreads();
    }

    const int b = bh >> 4;
    const int h = bh & 15;
    float il1 = 1.0f / l1;
    float il2 = 1.0f / l2;
    int row1 = q0 + wid*16 + g;
    int row2 = row1 + 8;
    __half* base1 = AO + ((size_t)(b*SEQ + row1))*DMODEL + h*DKH;
    __half* base2 = AO + ((size_t)(b*SEQ + row2))*DMODEL + h*DKH;
#pragma unroll
    for (int nb2 = 0; nb2 < 16; nb2++) {
        int col = nb2*8 + t4*2;
        *(__half2*)(base1 + col) = __floats2half2_rn(o[nb2][0]*il1, o[nb2][1]*il1);
        *(__half2*)(base2 + col) = __floats2half2_rn(o[nb2][2]*il2, o[nb2][3]*il2);
    }
}

// ---------------------------------------------------------------------------
extern "C" void kernel_launch(void* const* d_in, const int* in_sizes, int n_in,
                              void* d_out, int out_size)
{
    const float* x  = (const float*)d_in[0];
    const float* wq = (const float*)d_in[2];
    const float* wk = (const float*)d_in[3];
    const float* wv = (const float*)d_in[4];
    const float* wo = (const float*)d_in[5];
    float* out = (float*)d_out;

    float *q, *k, *v;
    __half *qh, *kh, *vh, *xh, *wqh, *wkh, *wvh, *woh, *aoh;
    cudaGetSymbolAddress((void**)&q,   g_Q);
    cudaGetSymbolAddress((void**)&k,   g_K);
    cudaGetSymbolAddress((void**)&v,   g_V);
    cudaGetSymbolAddress((void**)&qh,  g_Qh);
    cudaGetSymbolAddress((void**)&kh,  g_Kh);
    cudaGetSymbolAddress((void**)&vh,  g_Vh);
    cudaGetSymbolAddress((void**)&xh,  g_xh);
    cudaGetSymbolAddress((void**)&wqh, g_wqh);
    cudaGetSymbolAddress((void**)&wkh, g_wkh);
    cudaGetSymbolAddress((void**)&wvh, g_wvh);
    cudaGetSymbolAddress((void**)&woh, g_woh);
    cudaGetSymbolAddress((void**)&aoh, g_aoh);

    cudaFuncSetAttribute(gemm_f16<true>,  cudaFuncAttributeMaxDynamicSharedMemorySize, GEMM_SMEM_BYTES);
    cudaFuncSetAttribute(gemm_f16<false>, cudaFuncAttributeMaxDynamicSharedMemorySize, GEMM_SMEM_BYTES);
    cudaFuncSetAttribute(flash16, cudaFuncAttributeMaxDynamicSharedMemorySize, FL_SMEM_BYTES);

    // fp32 -> fp16 converts
    {
        int n4x = MROWS*DMODEL/4;
        int n4w = DMODEL*DMODEL/4;
        f32_to_f16<<<(n4x+255)/256, 256>>>(x, xh, n4x);
        dim3 wgrid((n4w+255)/256, 4);
        w_to_f16<<<wgrid, 256>>>(wq, wk, wv, wo, wqh, wkh, wvh, woh, n4w);
    }

    // QKV projection (fp32 out for accurate rope input)
    dim3 qkv_grid(DMODEL/GBN, MROWS/GBM, 3);    // (16, 16, 3)
    gemm_f16<true><<<qkv_grid, 256, GEMM_SMEM_BYTES>>>(xh, wqh, wkh, wvh, q, k, v);

    // rope + downconvert; V downconvert
    int npairs = BATCH*HEADS*SEQ*(DKH/2);
    rope_to_f16<<<(npairs + 255)/256, 256>>>(q, qh, 0.08838834764831845f);
    rope_to_f16<<<(npairs + 255)/256, 256>>>(k, kh, 1.0f);
    {
        int n4v = BATCH*HEADS*SEQ*DKH/4;
        f32_to_f16<<<(n4v+255)/256, 256>>>(v, vh, n4v);
    }

    // flash attention (fp16 in, fp16 out)
    dim3 fgrid(SEQ/BR, BATCH*HEADS);
    flash16<<<fgrid, 256, FL_SMEM_BYTES>>>(qh, kh, vh, aoh);

    // output projection
    dim3 wo_grid(DMODEL/GBN, MROWS/GBM, 1);     // (16, 16, 1)
    gemm_f16<false><<<wo_grid, 256, GEMM_SMEM_BYTES>>>(aoh, woh, nullptr, nullptr,
                                                       out, nullptr, nullptr);
}

// round 8
// speedup vs baseline: 1.1537x; 1.1537x over previous
#include <cuda_runtime.h>
#include <cuda_fp16.h>
#include <cuda_bf16.h>
#include <mma.h>
#include <math.h>
#include <cstdint>

using namespace nvcuda;

#define BATCH   2
#define SEQ     2048
#define DMODEL  2048
#define HEADS   16
#define DKH     128
#define MROWS   (BATCH*SEQ)

// ---------------- scratch (__device__ globals; allocation-free rule) -------
__device__ __half g_Qh[BATCH*HEADS*SEQ*DKH];
__device__ __half g_Kh[BATCH*HEADS*SEQ*DKH];
__device__ __half g_Vh[BATCH*HEADS*SEQ*DKH];
__device__ __half g_xh [MROWS*DMODEL];
__device__ __half g_wqh[DMODEL*DMODEL];
__device__ __half g_wkh[DMODEL*DMODEL];
__device__ __half g_wvh[DMODEL*DMODEL];
__device__ __half g_woh[DMODEL*DMODEL];
__device__ __half g_aoh[MROWS*DMODEL];

// ---------------------------------------------------------------------------
__global__ void f32_to_f16(const float* __restrict__ in, __half* __restrict__ out, int n4)
{
    int i = blockIdx.x * blockDim.x + threadIdx.x;
    if (i >= n4) return;
    float4 v = *(const float4*)(in + (size_t)i*4);
    *(__half2*)(out + (size_t)i*4)     = __floats2half2_rn(v.x, v.y);
    *(__half2*)(out + (size_t)i*4 + 2) = __floats2half2_rn(v.z, v.w);
}

__global__ void w_to_f16(const float* __restrict__ w0, const float* __restrict__ w1,
                         const float* __restrict__ w2, const float* __restrict__ w3,
                         __half* __restrict__ o0, __half* __restrict__ o1,
                         __half* __restrict__ o2, __half* __restrict__ o3, int n4)
{
    const float* in;
    __half* out;
    switch (blockIdx.y) {
        case 0: in = w0; out = o0; break;
        case 1: in = w1; out = o1; break;
        case 2: in = w2; out = o2; break;
        default: in = w3; out = o3; break;
    }
    int i = blockIdx.x * blockDim.x + threadIdx.x;
    if (i >= n4) return;
    float4 v = *(const float4*)(in + (size_t)i*4);
    *(__half2*)(out + (size_t)i*4)     = __floats2half2_rn(v.x, v.y);
    *(__half2*)(out + (size_t)i*4 + 2) = __floats2half2_rn(v.z, v.w);
}

// ---------------------------------------------------------------------------
__device__ __forceinline__ void cp_async16(void* smem, const void* gmem)
{
    unsigned int s = (unsigned int)__cvta_generic_to_shared(smem);
    asm volatile("cp.async.cg.shared.global [%0], [%1], 16;\n" :: "r"(s), "l"(gmem));
}
__device__ __forceinline__ void cp_commit() { asm volatile("cp.async.commit_group;\n"); }
template<int N> __device__ __forceinline__ void cp_wait() { asm volatile("cp.async.wait_group %0;\n" :: "n"(N)); }

__device__ __forceinline__ unsigned int smaddr(const void* p)
{ return (unsigned int)__cvta_generic_to_shared(p); }

__device__ __forceinline__ void ldsm4(uint32_t* r, unsigned int a)
{
    asm volatile("ldmatrix.sync.aligned.m8n8.x4.shared.b16 {%0,%1,%2,%3}, [%4];"
                 : "=r"(r[0]), "=r"(r[1]), "=r"(r[2]), "=r"(r[3]) : "r"(a));
}
__device__ __forceinline__ void ldsm4t(uint32_t* r, unsigned int a)
{
    asm volatile("ldmatrix.sync.aligned.m8n8.x4.trans.shared.b16 {%0,%1,%2,%3}, [%4];"
                 : "=r"(r[0]), "=r"(r[1]), "=r"(r[2]), "=r"(r[3]) : "r"(a));
}
__device__ __forceinline__ void mma16816(float* d, const uint32_t* a, const uint32_t* b)
{
    asm volatile("mma.sync.aligned.m16n8k16.row.col.f32.f16.f16.f32 "
                 "{%0,%1,%2,%3},{%4,%5,%6,%7},{%8,%9},{%0,%1,%2,%3};"
                 : "+f"(d[0]), "+f"(d[1]), "+f"(d[2]), "+f"(d[3])
                 : "r"(a[0]), "r"(a[1]), "r"(a[2]), "r"(a[3]), "r"(b[0]), "r"(b[1]));
}

// ---------------------------------------------------------------------------
// fp16 WMMA GEMM, 128x128 CTA tile, 4-stage cp.async (R4 shape — known good).
//   C[m,n] = sum_k A[m,k] * W[n,k]
// QKV=true: blockIdx.z selects weight; epilogue fuses RoPE (z<2) + fp16
//           downconvert, scatters headwise into [b,h,s,dk] fp16.
// QKV=false: fp32 output, [m,n] row-major.
// ---------------------------------------------------------------------------
#define GSTAGES 4
#define GBK     32
#define GAP     40
#define GSTAGE_HALVES (2*128*GAP)
#define GEMM_SMEM_BYTES (GSTAGES*GSTAGE_HALVES*(int)sizeof(__half))
#define EPI_LD  132

template<bool QKV>
__global__ __launch_bounds__(256, 2)
void gemm_f16(const __half* __restrict__ A,
              const __half* __restrict__ W0, const __half* __restrict__ W1, const __half* __restrict__ W2,
              float* __restrict__ C0,
              __half* __restrict__ H0, __half* __restrict__ H1, __half* __restrict__ H2)
{
    extern __shared__ __half sm_h[];

    const __half* W = W0;
    if (QKV) {
        if (blockIdx.z == 1) W = W1;
        else if (blockIdx.z == 2) W = W2;
    }

    const int m0  = blockIdx.y * 128;
    const int n0  = blockIdx.x * 128;
    const int tid = threadIdx.x;
    const int wid = tid >> 5;
    const int wm  = wid & 1;
    const int wn  = wid >> 1;

    wmma::fragment<wmma::accumulator,16,16,16,float> c[4][2];
#pragma unroll
    for (int i = 0; i < 4; i++)
#pragma unroll
        for (int j = 0; j < 2; j++)
            wmma::fill_fragment(c[i][j], 0.0f);

    const int NT = 2048 / GBK;

    auto load_stage = [&](int kt) {
        __half* sA = sm_h + (kt & (GSTAGES-1)) * GSTAGE_HALVES;
        __half* sB = sA + 128*GAP;
        const int kbase = kt * GBK;
#pragma unroll
        for (int it = 0; it < 2; it++) {
            int idx = it*256 + tid;
            int row = idx >> 2, cc = idx & 3;
            cp_async16(&sA[row*GAP + cc*8], A + (size_t)(m0+row)*2048 + kbase + cc*8);
        }
#pragma unroll
        for (int it = 0; it < 2; it++) {
            int idx = it*256 + tid;
            int row = idx >> 2, cc = idx & 3;
            cp_async16(&sB[row*GAP + cc*8], W + (size_t)(n0+row)*2048 + kbase + cc*8);
        }
    };

#pragma unroll
    for (int s = 0; s < GSTAGES-1; s++) { load_stage(s); cp_commit(); }

    for (int kt = 0; kt < NT; kt++) {
        cp_wait<GSTAGES-2>();
        __syncthreads();
        if (kt + GSTAGES-1 < NT) load_stage(kt + GSTAGES-1);
        cp_commit();

        __half* sA = sm_h + (kt & (GSTAGES-1)) * GSTAGE_HALVES;
        __half* sB = sA + 128*GAP;
#pragma unroll
        for (int ks = 0; ks < 2; ks++) {
            wmma::fragment<wmma::matrix_a,16,16,16,__half,wmma::row_major> a[4];
            wmma::fragment<wmma::matrix_b,16,16,16,__half,wmma::col_major> b[2];
#pragma unroll
            for (int i = 0; i < 4; i++)
                wmma::load_matrix_sync(a[i], &sA[(wm*64 + i*16)*GAP + ks*16], GAP);
#pragma unroll
            for (int j = 0; j < 2; j++)
                wmma::load_matrix_sync(b[j], &sB[(wn*32 + j*16)*GAP + ks*16], GAP);
#pragma unroll
            for (int i = 0; i < 4; i++)
#pragma unroll
                for (int j = 0; j < 2; j++)
                    wmma::mma_sync(c[i][j], a[i], b[j], c[i][j]);
        }
    }

    if (QKV) {
        // ---- fused epilogue: accum -> smem -> RoPE/convert -> fp16 headwise
        __syncthreads();
        float* sc = (float*)sm_h;               // 128 x EPI_LD fp32 (67.6 KB)
#pragma unroll
        for (int i = 0; i < 4; i++)
#pragma unroll
            for (int j = 0; j < 2; j++)
                wmma::store_matrix_sync(&sc[(wm*64 + i*16)*EPI_LD + wn*32 + j*16],
                                        c[i][j], EPI_LD, wmma::mem_row_major);
        __syncthreads();

        const int b  = m0 / SEQ;
        const int s0 = m0 % SEQ;
        const int h  = blockIdx.x;
        const bool rope  = (blockIdx.z < 2);
        const float scale = (blockIdx.z == 0) ? 0.08838834764831845f : 1.0f;
        __half* H = (blockIdx.z == 0) ? H0 : ((blockIdx.z == 1) ? H1 : H2);

        for (int p = tid; p < 128*64; p += 256) {
            int r  = p >> 6;
            int dd = p & 63;
            float x1 = sc[r*EPI_LD + 2*dd];
            float x2 = sc[r*EPI_LD + 2*dd + 1];
            float y1, y2;
            if (rope) {
                float freq = exp2f(-13.287712379549449f * ((float)(2*dd) * (1.0f/128.0f)));
                float ang  = (float)(s0 + r) * freq;
                float sn, cs;
                sincosf(ang, &sn, &cs);
                y1 = (x1*cs - x2*sn) * scale;
                y2 = (x1*sn + x2*cs) * scale;
            } else {
                y1 = x1; y2 = x2;
            }
            *(__half2*)(H + ((size_t)(b*HEADS + h)*SEQ + s0 + r)*DKH + 2*dd)
                = __floats2half2_rn(y1, y2);
        }
    } else {
        float* base = C0 + (size_t)m0*DMODEL + n0;
#pragma unroll
        for (int i = 0; i < 4; i++)
#pragma unroll
            for (int j = 0; j < 2; j++)
                wmma::store_matrix_sync(base + (size_t)(wm*64 + i*16)*DMODEL + wn*32 + j*16,
                                        c[i][j], DMODEL, wmma::mem_row_major);
    }
}

// ---------------------------------------------------------------------------
// FA2-style fp16 flash attention (causal) — unchanged from R4 (known good).
// ---------------------------------------------------------------------------
#define BR 128
#define BC 64
#define DPAD 136
#define KV_STAGE_HALVES (2*BC*DPAD)
#define FL_SMEM_BYTES (2*KV_STAGE_HALVES*(int)sizeof(__half))

__global__ __launch_bounds__(256, 1)
void flash16(const __half* __restrict__ Q, const __half* __restrict__ K,
             const __half* __restrict__ V, __half* __restrict__ AO)
{
    extern __shared__ __half smf[];
    __half* buf0 = smf;
    __half* buf1 = smf + KV_STAGE_HALVES;

    const int qt  = (gridDim.x - 1) - blockIdx.x;
    const int bh  = blockIdx.y;
    const int q0  = qt * BR;
    const int tid = threadIdx.x;
    const int lane = tid & 31;
    const int wid  = tid >> 5;
    const int g    = lane >> 2;
    const int t4   = lane & 3;
    const int l8   = lane & 7;

    const __half* Qg = Q + ((size_t)bh * SEQ + q0) * DKH;
    for (int i = tid; i < BR*16; i += 256) {
        int r = i >> 4, c = i & 15;
        cp_async16(&buf1[r*DPAD + c*8], Qg + (size_t)r*DKH + c*8);
    }
    cp_commit();
    cp_wait<0>();
    __syncthreads();

    uint32_t qf[8][4];
    {
        int row  = wid*16 + ((lane >> 3) & 1)*8 + l8;
        int koff = (lane >> 4) * 8;
#pragma unroll
        for (int ks = 0; ks < 8; ks++)
            ldsm4(qf[ks], smaddr(&buf1[row*DPAD + ks*16 + koff]));
    }
    __syncthreads();

    float o[16][4];
#pragma unroll
    for (int i = 0; i < 16; i++)
#pragma unroll
        for (int j = 0; j < 4; j++) o[i][j] = 0.0f;
    float m1 = -1e30f, m2 = -1e30f, l1 = 0.0f, l2 = 0.0f;

    auto loadKV = [&](int t, int stage) {
        const __half* Kg = K + ((size_t)bh * SEQ + t*BC) * DKH;
        const __half* Vg = V + ((size_t)bh * SEQ + t*BC) * DKH;
        __half* s  = stage ? buf1 : buf0;
        __half* sv = s + BC*DPAD;
#pragma unroll
        for (int it = 0; it < 4; it++) {
            int i = it*256 + tid;
            int r = i >> 4, c = i & 15;
            cp_async16(&s[r*DPAD + c*8],  Kg + (size_t)r*DKH + c*8);
        }
#pragma unroll
        for (int it = 0; it < 4; it++) {
            int i = it*256 + tid;
            int r = i >> 4, c = i & 15;
            cp_async16(&sv[r*DPAD + c*8], Vg + (size_t)r*DKH + c*8);
        }
    };

    const int nt = 2*qt + 2;
    loadKV(0, 0);
    cp_commit();

    for (int t = 0; t < nt; t++) {
        if (t + 1 < nt) { loadKV(t+1, (t+1) & 1); cp_commit(); cp_wait<1>(); }
        else            { cp_wait<0>(); }
        __syncthreads();

        __half* sk = (t & 1) ? buf1 : buf0;
        __half* sv = sk + BC*DPAD;

        float s[8][4];
#pragma unroll
        for (int i = 0; i < 8; i++)
#pragma unroll
            for (int j = 0; j < 4; j++) s[i][j] = 0.0f;

#pragma unroll
        for (int ks = 0; ks < 8; ks++) {
#pragma unroll
            for (int nb2 = 0; nb2 < 4; nb2++) {
                uint32_t kf[4];
                int row  = nb2*16 + ((lane >> 4) & 1)*8 + l8;
                int koff = ks*16 + ((lane >> 3) & 1)*8;
                ldsm4(kf, smaddr(&sk[row*DPAD + koff]));
                mma16816(s[nb2*2],     qf[ks], kf);
                mma16816(s[nb2*2 + 1], qf[ks], kf + 2);
            }
        }

        if (t >= 2*qt) {
            int row1 = q0 + wid*16 + g;
            int row2 = row1 + 8;
            int cb   = t*BC + t4*2;
#pragma unroll
            for (int nb = 0; nb < 8; nb++) {
                int c0 = cb + nb*8, c1 = c0 + 1;
                if (c0 > row1) s[nb][0] = -1e30f;
                if (c1 > row1) s[nb][1] = -1e30f;
                if (c0 > row2) s[nb][2] = -1e30f;
                if (c1 > row2) s[nb][3] = -1e30f;
            }
        }

        float mx1 = -1e30f, mx2 = -1e30f;
#pragma unroll
        for (int nb = 0; nb < 8; nb++) {
            mx1 = fmaxf(mx1, fmaxf(s[nb][0], s[nb][1]));
            mx2 = fmaxf(mx2, fmaxf(s[nb][2], s[nb][3]));
        }
        mx1 = fmaxf(mx1, __shfl_xor_sync(0xffffffffu, mx1, 1));
        mx1 = fmaxf(mx1, __shfl_xor_sync(0xffffffffu, mx1, 2));
        mx2 = fmaxf(mx2, __shfl_xor_sync(0xffffffffu, mx2, 1));
        mx2 = fmaxf(mx2, __shfl_xor_sync(0xffffffffu, mx2, 2));

        float m1n = fmaxf(m1, mx1);
        float m2n = fmaxf(m2, mx2);
        float a1  = __expf(m1 - m1n);
        float a2  = __expf(m2 - m2n);

        uint32_t pf[4][4];
        float ls1 = 0.0f, ls2 = 0.0f;
#pragma unroll
        for (int nb = 0; nb < 8; nb++) {
            float p0 = __expf(s[nb][0] - m1n);
            float p1 = __expf(s[nb][1] - m1n);
            float p2 = __expf(s[nb][2] - m2n);
            float p3 = __expf(s[nb][3] - m2n);
            ls1 += p0 + p1;
            ls2 += p2 + p3;
            __half2 h01 = __floats2half2_rn(p0, p1);
            __half2 h23 = __floats2half2_rn(p2, p3);
            int ks = nb >> 1;
            if ((nb & 1) == 0) {
                pf[ks][0] = *(uint32_t*)&h01;
                pf[ks][1] = *(uint32_t*)&h23;
            } else {
                pf[ks][2] = *(uint32_t*)&h01;
                pf[ks][3] = *(uint32_t*)&h23;
            }
        }
        ls1 += __shfl_xor_sync(0xffffffffu, ls1, 1);
        ls1 += __shfl_xor_sync(0xffffffffu, ls1, 2);
        ls2 += __shfl_xor_sync(0xffffffffu, ls2, 1);
        ls2 += __shfl_xor_sync(0xffffffffu, ls2, 2);

        l1 = l1*a1 + ls1;
        l2 = l2*a2 + ls2;
        m1 = m1n; m2 = m2n;

#pragma unroll
        for (int nb2 = 0; nb2 < 16; nb2++) {
            o[nb2][0] *= a1; o[nb2][1] *= a1;
            o[nb2][2] *= a2; o[nb2][3] *= a2;
        }

#pragma unroll
        for (int ks = 0; ks < 4; ks++) {
#pragma unroll
            for (int nbp = 0; nbp < 8; nbp++) {
                uint32_t vf[4];
                int vrow = ks*16 + ((lane >> 3) & 1)*8 + l8;
                int vcol = nbp*16 + (lane >> 4)*8;
                ldsm4t(vf, smaddr(&sv[vrow*DPAD + vcol]));
                mma16816(o[nbp*2],     pf[ks], vf);
                mma16816(o[nbp*2 + 1], pf[ks], vf + 2);
            }
        }

        __syncthreads();
    }

    const int b = bh >> 4;
    const int h = bh & 15;
    float il1 = 1.0f / l1;
    float il2 = 1.0f / l2;
    int row1 = q0 + wid*16 + g;
    int row2 = row1 + 8;
    __half* base1 = AO + ((size_t)(b*SEQ + row1))*DMODEL + h*DKH;
    __half* base2 = AO + ((size_t)(b*SEQ + row2))*DMODEL + h*DKH;
#pragma unroll
    for (int nb2 = 0; nb2 < 16; nb2++) {
        int col = nb2*8 + t4*2;
        *(__half2*)(base1 + col) = __floats2half2_rn(o[nb2][0]*il1, o[nb2][1]*il1);
        *(__half2*)(base2 + col) = __floats2half2_rn(o[nb2][2]*il2, o[nb2][3]*il2);
    }
}

// ---------------------------------------------------------------------------
extern "C" void kernel_launch(void* const* d_in, const int* in_sizes, int n_in,
                              void* d_out, int out_size)
{
    const float* x  = (const float*)d_in[0];
    const float* wq = (const float*)d_in[2];
    const float* wk = (const float*)d_in[3];
    const float* wv = (const float*)d_in[4];
    const float* wo = (const float*)d_in[5];
    float* out = (float*)d_out;

    __half *qh, *kh, *vh, *xh, *wqh, *wkh, *wvh, *woh, *aoh;
    cudaGetSymbolAddress((void**)&qh,  g_Qh);
    cudaGetSymbolAddress((void**)&kh,  g_Kh);
    cudaGetSymbolAddress((void**)&vh,  g_Vh);
    cudaGetSymbolAddress((void**)&xh,  g_xh);
    cudaGetSymbolAddress((void**)&wqh, g_wqh);
    cudaGetSymbolAddress((void**)&wkh, g_wkh);
    cudaGetSymbolAddress((void**)&wvh, g_wvh);
    cudaGetSymbolAddress((void**)&woh, g_woh);
    cudaGetSymbolAddress((void**)&aoh, g_aoh);

    cudaFuncSetAttribute(gemm_f16<true>,  cudaFuncAttributeMaxDynamicSharedMemorySize, GEMM_SMEM_BYTES);
    cudaFuncSetAttribute(gemm_f16<false>, cudaFuncAttributeMaxDynamicSharedMemorySize, GEMM_SMEM_BYTES);
    cudaFuncSetAttribute(flash16, cudaFuncAttributeMaxDynamicSharedMemorySize, FL_SMEM_BYTES);

    // fp32 -> fp16 converts
    {
        int n4x = MROWS*DMODEL/4;
        int n4w = DMODEL*DMODEL/4;
        f32_to_f16<<<(n4x+255)/256, 256>>>(x, xh, n4x);
        dim3 wgrid((n4w+255)/256, 4);
        w_to_f16<<<wgrid, 256>>>(wq, wk, wv, wo, wqh, wkh, wvh, woh, n4w);
    }

    // QKV projection with fused RoPE + fp16 epilogue
    dim3 qkv_grid(DMODEL/128, MROWS/128, 3);
    gemm_f16<true><<<qkv_grid, 256, GEMM_SMEM_BYTES>>>(xh, wqh, wkh, wvh,
                                                       nullptr, qh, kh, vh);

    // flash attention (fp16 in, fp16 out)
    dim3 fgrid(SEQ/BR, BATCH*HEADS);
    flash16<<<fgrid, 256, FL_SMEM_BYTES>>>(qh, kh, vh, aoh);

    // output projection (fp32 out)
    dim3 wo_grid(DMODEL/128, MROWS/128, 1);
    gemm_f16<false><<<wo_grid, 256, GEMM_SMEM_BYTES>>>(aoh, woh, nullptr, nullptr,
                                                       out, nullptr, nullptr, nullptr);
}

// round 9
// speedup vs baseline: 1.1817x; 1.0243x over previous
#include <cuda_runtime.h>
#include <cuda_fp16.h>
#include <cuda_bf16.h>
#include <mma.h>
#include <math.h>
#include <cstdint>

using namespace nvcuda;

#define BATCH   2
#define SEQ     2048
#define DMODEL  2048
#define HEADS   16
#define DKH     128
#define MROWS   (BATCH*SEQ)

// ---------------- scratch (__device__ globals; allocation-free rule) -------
__device__ __half g_Qh[BATCH*HEADS*SEQ*DKH];
__device__ __half g_Kh[BATCH*HEADS*SEQ*DKH];
__device__ __half g_Vh[BATCH*HEADS*SEQ*DKH];
__device__ __half g_xh [MROWS*DMODEL];
__device__ __half g_wqh[DMODEL*DMODEL];
__device__ __half g_wkh[DMODEL*DMODEL];
__device__ __half g_wvh[DMODEL*DMODEL];
__device__ __half g_woh[DMODEL*DMODEL];
__device__ __half g_aoh[MROWS*DMODEL];

// ---------------------------------------------------------------------------
__global__ void f32_to_f16(const float* __restrict__ in, __half* __restrict__ out, int n4)
{
    int i = blockIdx.x * blockDim.x + threadIdx.x;
    if (i >= n4) return;
    float4 v = *(const float4*)(in + (size_t)i*4);
    *(__half2*)(out + (size_t)i*4)     = __floats2half2_rn(v.x, v.y);
    *(__half2*)(out + (size_t)i*4 + 2) = __floats2half2_rn(v.z, v.w);
}

__global__ void w_to_f16(const float* __restrict__ w0, const float* __restrict__ w1,
                         const float* __restrict__ w2, const float* __restrict__ w3,
                         __half* __restrict__ o0, __half* __restrict__ o1,
                         __half* __restrict__ o2, __half* __restrict__ o3, int n4)
{
    const float* in;
    __half* out;
    switch (blockIdx.y) {
        case 0: in = w0; out = o0; break;
        case 1: in = w1; out = o1; break;
        case 2: in = w2; out = o2; break;
        default: in = w3; out = o3; break;
    }
    int i = blockIdx.x * blockDim.x + threadIdx.x;
    if (i >= n4) return;
    float4 v = *(const float4*)(in + (size_t)i*4);
    *(__half2*)(out + (size_t)i*4)     = __floats2half2_rn(v.x, v.y);
    *(__half2*)(out + (size_t)i*4 + 2) = __floats2half2_rn(v.z, v.w);
}

// ---------------------------------------------------------------------------
__device__ __forceinline__ void cp_async16(void* smem, const void* gmem)
{
    unsigned int s = (unsigned int)__cvta_generic_to_shared(smem);
    asm volatile("cp.async.cg.shared.global [%0], [%1], 16;\n" :: "r"(s), "l"(gmem));
}
__device__ __forceinline__ void cp_commit() { asm volatile("cp.async.commit_group;\n"); }
template<int N> __device__ __forceinline__ void cp_wait() { asm volatile("cp.async.wait_group %0;\n" :: "n"(N)); }

__device__ __forceinline__ unsigned int smaddr(const void* p)
{ return (unsigned int)__cvta_generic_to_shared(p); }

__device__ __forceinline__ void ldsm4(uint32_t* r, unsigned int a)
{
    asm volatile("ldmatrix.sync.aligned.m8n8.x4.shared.b16 {%0,%1,%2,%3}, [%4];"
                 : "=r"(r[0]), "=r"(r[1]), "=r"(r[2]), "=r"(r[3]) : "r"(a));
}
__device__ __forceinline__ void ldsm4t(uint32_t* r, unsigned int a)
{
    asm volatile("ldmatrix.sync.aligned.m8n8.x4.trans.shared.b16 {%0,%1,%2,%3}, [%4];"
                 : "=r"(r[0]), "=r"(r[1]), "=r"(r[2]), "=r"(r[3]) : "r"(a));
}
__device__ __forceinline__ void mma16816(float* d, const uint32_t* a, const uint32_t* b)
{
    asm volatile("mma.sync.aligned.m16n8k16.row.col.f32.f16.f16.f32 "
                 "{%0,%1,%2,%3},{%4,%5,%6,%7},{%8,%9},{%0,%1,%2,%3};"
                 : "+f"(d[0]), "+f"(d[1]), "+f"(d[2]), "+f"(d[3])
                 : "r"(a[0]), "r"(a[1]), "r"(a[2]), "r"(a[3]), "r"(b[0]), "r"(b[1]));
}

#define BARSYNC(id, n)   asm volatile("bar.sync %0, %1;"   :: "r"(id), "r"(n) : "memory")
#define BARARRIVE(id, n) asm volatile("bar.arrive %0, %1;" :: "r"(id), "r"(n) : "memory")

// ---------------------------------------------------------------------------
// fp16 WMMA GEMM, 128x128 CTA tile, 4-stage cp.async (R8 — unchanged).
// ---------------------------------------------------------------------------
#define GSTAGES 4
#define GBK     32
#define GAP     40
#define GSTAGE_HALVES (2*128*GAP)
#define GEMM_SMEM_BYTES (GSTAGES*GSTAGE_HALVES*(int)sizeof(__half))
#define EPI_LD  132

template<bool QKV>
__global__ __launch_bounds__(256, 2)
void gemm_f16(const __half* __restrict__ A,
              const __half* __restrict__ W0, const __half* __restrict__ W1, const __half* __restrict__ W2,
              float* __restrict__ C0,
              __half* __restrict__ H0, __half* __restrict__ H1, __half* __restrict__ H2)
{
    extern __shared__ __half sm_h[];

    const __half* W = W0;
    if (QKV) {
        if (blockIdx.z == 1) W = W1;
        else if (blockIdx.z == 2) W = W2;
    }

    const int m0  = blockIdx.y * 128;
    const int n0  = blockIdx.x * 128;
    const int tid = threadIdx.x;
    const int wid = tid >> 5;
    const int wm  = wid & 1;
    const int wn  = wid >> 1;

    wmma::fragment<wmma::accumulator,16,16,16,float> c[4][2];
#pragma unroll
    for (int i = 0; i < 4; i++)
#pragma unroll
        for (int j = 0; j < 2; j++)
            wmma::fill_fragment(c[i][j], 0.0f);

    const int NT = 2048 / GBK;

    auto load_stage = [&](int kt) {
        __half* sA = sm_h + (kt & (GSTAGES-1)) * GSTAGE_HALVES;
        __half* sB = sA + 128*GAP;
        const int kbase = kt * GBK;
#pragma unroll
        for (int it = 0; it < 2; it++) {
            int idx = it*256 + tid;
            int row = idx >> 2, cc = idx & 3;
            cp_async16(&sA[row*GAP + cc*8], A + (size_t)(m0+row)*2048 + kbase + cc*8);
        }
#pragma unroll
        for (int it = 0; it < 2; it++) {
            int idx = it*256 + tid;
            int row = idx >> 2, cc = idx & 3;
            cp_async16(&sB[row*GAP + cc*8], W + (size_t)(n0+row)*2048 + kbase + cc*8);
        }
    };

#pragma unroll
    for (int s = 0; s < GSTAGES-1; s++) { load_stage(s); cp_commit(); }

    for (int kt = 0; kt < NT; kt++) {
        cp_wait<GSTAGES-2>();
        __syncthreads();
        if (kt + GSTAGES-1 < NT) load_stage(kt + GSTAGES-1);
        cp_commit();

        __half* sA = sm_h + (kt & (GSTAGES-1)) * GSTAGE_HALVES;
        __half* sB = sA + 128*GAP;
#pragma unroll
        for (int ks = 0; ks < 2; ks++) {
            wmma::fragment<wmma::matrix_a,16,16,16,__half,wmma::row_major> a[4];
            wmma::fragment<wmma::matrix_b,16,16,16,__half,wmma::col_major> b[2];
#pragma unroll
            for (int i = 0; i < 4; i++)
                wmma::load_matrix_sync(a[i], &sA[(wm*64 + i*16)*GAP + ks*16], GAP);
#pragma unroll
            for (int j = 0; j < 2; j++)
                wmma::load_matrix_sync(b[j], &sB[(wn*32 + j*16)*GAP + ks*16], GAP);
#pragma unroll
            for (int i = 0; i < 4; i++)
#pragma unroll
                for (int j = 0; j < 2; j++)
                    wmma::mma_sync(c[i][j], a[i], b[j], c[i][j]);
        }
    }

    if (QKV) {
        __syncthreads();
        float* sc = (float*)sm_h;
#pragma unroll
        for (int i = 0; i < 4; i++)
#pragma unroll
            for (int j = 0; j < 2; j++)
                wmma::store_matrix_sync(&sc[(wm*64 + i*16)*EPI_LD + wn*32 + j*16],
                                        c[i][j], EPI_LD, wmma::mem_row_major);
        __syncthreads();

        const int b  = m0 / SEQ;
        const int s0 = m0 % SEQ;
        const int h  = blockIdx.x;
        const bool rope  = (blockIdx.z < 2);
        const float scale = (blockIdx.z == 0) ? 0.08838834764831845f : 1.0f;
        __half* H = (blockIdx.z == 0) ? H0 : ((blockIdx.z == 1) ? H1 : H2);

        for (int p = tid; p < 128*64; p += 256) {
            int r  = p >> 6;
            int dd = p & 63;
            float x1 = sc[r*EPI_LD + 2*dd];
            float x2 = sc[r*EPI_LD + 2*dd + 1];
            float y1, y2;
            if (rope) {
                float freq = exp2f(-13.287712379549449f * ((float)(2*dd) * (1.0f/128.0f)));
                float ang  = (float)(s0 + r) * freq;
                float sn, cs;
                sincosf(ang, &sn, &cs);
                y1 = (x1*cs - x2*sn) * scale;
                y2 = (x1*sn + x2*cs) * scale;
            } else {
                y1 = x1; y2 = x2;
            }
            *(__half2*)(H + ((size_t)(b*HEADS + h)*SEQ + s0 + r)*DKH + 2*dd)
                = __floats2half2_rn(y1, y2);
        }
    } else {
        float* base = C0 + (size_t)m0*DMODEL + n0;
#pragma unroll
        for (int i = 0; i < 4; i++)
#pragma unroll
            for (int j = 0; j < 2; j++)
                wmma::store_matrix_sync(base + (size_t)(wm*64 + i*16)*DMODEL + wn*32 + j*16,
                                        c[i][j], DMODEL, wmma::mem_row_major);
    }
}

// ---------------------------------------------------------------------------
// Warp-specialized flash attention (causal). BR=64, BC=64, d=128.
// Warps 0-3: S = QK^T + softmax -> P(fp16) + alpha to smem.
// Warps 4-7: o = o*alpha + P V; output.
// Named barriers: FULL{0,1}=1,2  EMPTY{0,1}=3,4  S-group=5  PV-group=6.
// 2 CTAs/SM (regs capped 128, smem 88.8 KB).
// ---------------------------------------------------------------------------
#define FBR 64
#define FBC 64
#define FDP 136
#define FPP 72
#define FK0 0
#define FK1 8704
#define FV0 17408
#define FV1 26112
#define FP0 34816
#define FP1 39424
#define FHALVES 44032
#define FWS_SMEM (FHALVES*2 + 192*4)

__global__ __launch_bounds__(256, 2)
void flash_ws(const __half* __restrict__ Q, const __half* __restrict__ K,
              const __half* __restrict__ V, __half* __restrict__ AO)
{
    extern __shared__ __half smf[];
    float* alpha0 = (float*)((char*)smf + FHALVES*2);
    float* alpha1 = alpha0 + 64;
    float* lrow   = alpha1 + 64;

    const int qt  = (gridDim.x - 1) - blockIdx.x;    // heavy tiles first
    const int bh  = blockIdx.y;
    const int q0  = qt * FBR;
    const int tid  = threadIdx.x;
    const int lane = tid & 31;
    const int wid  = tid >> 5;
    const int g    = lane >> 2;
    const int t4   = lane & 3;
    const int l8   = lane & 7;
    const int nt   = qt + 1;
    const bool isS = (wid < 4);
    const int  w   = isS ? wid : (wid - 4);          // row-group 0..3
    const int ctid = tid & 127;                      // id within group

    // ---- stage Q into P region (stride FDP; 64x136 fits in P0+P1)
    const __half* Qg = Q + ((size_t)bh*SEQ + q0)*DKH;
#pragma unroll
    for (int it = 0; it < 4; it++) {
        int i = it*256 + tid;
        int r = i >> 4, c = i & 15;
        cp_async16(&smf[FP0 + r*FDP + c*8], Qg + (size_t)r*DKH + c*8);
    }
    cp_commit();

    // ---- prologue: S group loads K(0), PV group loads V(0)
    if (isS) {
        const __half* Kg = K + ((size_t)bh*SEQ)*DKH;
#pragma unroll
        for (int it = 0; it < 8; it++) {
            int i = it*128 + ctid;
            int r = i >> 4, c = i & 15;
            cp_async16(&smf[FK0 + r*FDP + c*8], Kg + (size_t)r*DKH + c*8);
        }
    } else {
        const __half* Vg = V + ((size_t)bh*SEQ)*DKH;
#pragma unroll
        for (int it = 0; it < 8; it++) {
            int i = it*128 + ctid;
            int r = i >> 4, c = i & 15;
            cp_async16(&smf[FV0 + r*FDP + c*8], Vg + (size_t)r*DKH + c*8);
        }
    }
    cp_commit();
    cp_wait<1>();                 // Q staged
    __syncthreads();

    uint32_t qf[8][4];
    if (isS) {
        int row  = w*16 + ((lane >> 3) & 1)*8 + l8;
        int koff = (lane >> 4) * 8;
#pragma unroll
        for (int ks = 0; ks < 8; ks++)
            ldsm4(qf[ks], smaddr(&smf[FP0 + row*FDP + ks*16 + koff]));
    }
    __syncthreads();              // Q reads done; P region free

    if (isS) {
        // ================= S / softmax warps =================
        float m1 = -1e30f, m2 = -1e30f, l1 = 0.0f, l2 = 0.0f;
        for (int t = 0; t < nt; t++) {
            if (t + 1 < nt) {
                const __half* Kg = K + ((size_t)bh*SEQ + (size_t)(t+1)*FBC)*DKH;
                __half* kb = &smf[((t+1) & 1) ? FK1 : FK0];
#pragma unroll
                for (int it = 0; it < 8; it++) {
                    int i = it*128 + ctid;
                    int r = i >> 4, c = i & 15;
                    cp_async16(&kb[r*FDP + c*8], Kg + (size_t)r*DKH + c*8);
                }
                cp_commit();
                cp_wait<1>();
            } else cp_wait<0>();
            BARSYNC(5, 128);      // K(t) visible to all S warps

            __half* sk = &smf[(t & 1) ? FK1 : FK0];
            float s[8][4];
#pragma unroll
            for (int i = 0; i < 8; i++)
#pragma unroll
                for (int j = 0; j < 4; j++) s[i][j] = 0.0f;

#pragma unroll
            for (int ks = 0; ks < 8; ks++) {
#pragma unroll
                for (int nb2 = 0; nb2 < 4; nb2++) {
                    uint32_t kf[4];
                    int row  = nb2*16 + ((lane >> 4) & 1)*8 + l8;
                    int koff = ks*16 + ((lane >> 3) & 1)*8;
                    ldsm4(kf, smaddr(&sk[row*FDP + koff]));
                    mma16816(s[nb2*2],     qf[ks], kf);
                    mma16816(s[nb2*2 + 1], qf[ks], kf + 2);
                }
            }

            if (t == nt - 1) {    // diagonal tile
                int row1 = q0 + w*16 + g;
                int row2 = row1 + 8;
                int cb   = t*FBC + t4*2;
#pragma unroll
                for (int nb = 0; nb < 8; nb++) {
                    int c0 = cb + nb*8, c1 = c0 + 1;
                    if (c0 > row1) s[nb][0] = -1e30f;
                    if (c1 > row1) s[nb][1] = -1e30f;
                    if (c0 > row2) s[nb][2] = -1e30f;
                    if (c1 > row2) s[nb][3] = -1e30f;
                }
            }

            float mx1 = -1e30f, mx2 = -1e30f;
#pragma unroll
            for (int nb = 0; nb < 8; nb++) {
                mx1 = fmaxf(mx1, fmaxf(s[nb][0], s[nb][1]));
                mx2 = fmaxf(mx2, fmaxf(s[nb][2], s[nb][3]));
            }
            mx1 = fmaxf(mx1, __shfl_xor_sync(0xffffffffu, mx1, 1));
            mx1 = fmaxf(mx1, __shfl_xor_sync(0xffffffffu, mx1, 2));
            mx2 = fmaxf(mx2, __shfl_xor_sync(0xffffffffu, mx2, 1));
            mx2 = fmaxf(mx2, __shfl_xor_sync(0xffffffffu, mx2, 2));

            float m1n = fmaxf(m1, mx1);
            float m2n = fmaxf(m2, mx2);
            float a1  = __expf(m1 - m1n);
            float a2  = __expf(m2 - m2n);

            float ls1 = 0.0f, ls2 = 0.0f;
            __half2 pp1[8], pp2[8];
#pragma unroll
            for (int nb = 0; nb < 8; nb++) {
                float p0 = __expf(s[nb][0] - m1n);
                float p1 = __expf(s[nb][1] - m1n);
                float p2 = __expf(s[nb][2] - m2n);
                float p3 = __expf(s[nb][3] - m2n);
                ls1 += p0 + p1;
                ls2 += p2 + p3;
                pp1[nb] = __floats2half2_rn(p0, p1);
                pp2[nb] = __floats2half2_rn(p2, p3);
            }
            ls1 += __shfl_xor_sync(0xffffffffu, ls1, 1);
            ls1 += __shfl_xor_sync(0xffffffffu, ls1, 2);
            ls2 += __shfl_xor_sync(0xffffffffu, ls2, 1);
            ls2 += __shfl_xor_sync(0xffffffffu, ls2, 2);

            l1 = l1*a1 + ls1;
            l2 = l2*a2 + ls2;
            m1 = m1n; m2 = m2n;

            if (t >= 2) BARSYNC(3 + (t & 1), 256);   // wait P buffer empty

            __half* pb = &smf[(t & 1) ? FP1 : FP0];
            float*  ab = (t & 1) ? alpha1 : alpha0;
            int r1o = (w*16 + g)*FPP;
            int r2o = r1o + 8*FPP;
#pragma unroll
            for (int nb = 0; nb < 8; nb++) {
                *(__half2*)&pb[r1o + nb*8 + t4*2] = pp1[nb];
                *(__half2*)&pb[r2o + nb*8 + t4*2] = pp2[nb];
            }
            if (t4 == 0) {
                ab[w*16 + g]     = a1;
                ab[w*16 + g + 8] = a2;
            }
            BARARRIVE(1 + (t & 1), 256);             // P(t) full
            BARSYNC(5, 128);                         // all S done with K(t)
        }
        if (t4 == 0) {
            lrow[w*16 + g]     = l1;
            lrow[w*16 + g + 8] = l2;
        }
    } else {
        // ================= PV / output warps =================
        float o[16][4];
#pragma unroll
        for (int i = 0; i < 16; i++)
#pragma unroll
            for (int j = 0; j < 4; j++) o[i][j] = 0.0f;

        for (int t = 0; t < nt; t++) {
            if (t + 1 < nt) {
                const __half* Vg = V + ((size_t)bh*SEQ + (size_t)(t+1)*FBC)*DKH;
                __half* vb = &smf[((t+1) & 1) ? FV1 : FV0];
#pragma unroll
                for (int it = 0; it < 8; it++) {
                    int i = it*128 + ctid;
                    int r = i >> 4, c = i & 15;
                    cp_async16(&vb[r*FDP + c*8], Vg + (size_t)r*DKH + c*8);
                }
                cp_commit();
                cp_wait<1>();
            } else cp_wait<0>();
            BARSYNC(6, 128);                         // V(t) visible
            BARSYNC(1 + (t & 1), 256);               // wait P(t) full

            float* ab = (t & 1) ? alpha1 : alpha0;
            float a1 = ab[w*16 + g];
            float a2 = ab[w*16 + g + 8];
#pragma unroll
            for (int nb2 = 0; nb2 < 16; nb2++) {
                o[nb2][0] *= a1; o[nb2][1] *= a1;
                o[nb2][2] *= a2; o[nb2][3] *= a2;
            }

            __half* pb = &smf[(t & 1) ? FP1 : FP0];
            __half* sv = &smf[(t & 1) ? FV1 : FV0];
#pragma unroll
            for (int ks = 0; ks < 4; ks++) {
                uint32_t pf[4];
                {
                    int prow = w*16 + ((lane >> 3) & 1)*8 + l8;
                    int pcol = ks*16 + (lane >> 4)*8;
                    ldsm4(pf, smaddr(&pb[prow*FPP + pcol]));
                }
#pragma unroll
                for (int nbp = 0; nbp < 8; nbp++) {
                    uint32_t vf[4];
                    int vrow = ks*16 + ((lane >> 3) & 1)*8 + l8;
                    int vcol = nbp*16 + (lane >> 4)*8;
                    ldsm4t(vf, smaddr(&sv[vrow*FDP + vcol]));
                    mma16816(o[nbp*2],     pf, vf);
                    mma16816(o[nbp*2 + 1], pf, vf + 2);
                }
            }

            if (t + 2 < nt) BARARRIVE(3 + (t & 1), 256);  // P buffer empty
            BARSYNC(6, 128);                               // all PV done with V(t)
        }

        __syncthreads();   // (paired with S side below)
        const int b = bh >> 4;
        const int h = bh & 15;
        float il1 = 1.0f / lrow[w*16 + g];
        float il2 = 1.0f / lrow[w*16 + g + 8];
        int row1 = q0 + w*16 + g;
        int row2 = row1 + 8;
        __half* base1 = AO + ((size_t)(b*SEQ + row1))*DMODEL + h*DKH;
        __half* base2 = AO + ((size_t)(b*SEQ + row2))*DMODEL + h*DKH;
#pragma unroll
        for (int nb2 = 0; nb2 < 16; nb2++) {
            int col = nb2*8 + t4*2;
            *(__half2*)(base1 + col) = __floats2half2_rn(o[nb2][0]*il1, o[nb2][1]*il1);
            *(__half2*)(base2 + col) = __floats2half2_rn(o[nb2][2]*il2, o[nb2][3]*il2);
        }
        return;
    }
    __syncthreads();   // S side: pairs with PV side's pre-epilogue sync
}

// ---------------------------------------------------------------------------
extern "C" void kernel_launch(void* const* d_in, const int* in_sizes, int n_in,
                              void* d_out, int out_size)
{
    const float* x  = (const float*)d_in[0];
    const float* wq = (const float*)d_in[2];
    const float* wk = (const float*)d_in[3];
    const float* wv = (const float*)d_in[4];
    const float* wo = (const float*)d_in[5];
    float* out = (float*)d_out;

    __half *qh, *kh, *vh, *xh, *wqh, *wkh, *wvh, *woh, *aoh;
    cudaGetSymbolAddress((void**)&qh,  g_Qh);
    cudaGetSymbolAddress((void**)&kh,  g_Kh);
    cudaGetSymbolAddress((void**)&vh,  g_Vh);
    cudaGetSymbolAddress((void**)&xh,  g_xh);
    cudaGetSymbolAddress((void**)&wqh, g_wqh);
    cudaGetSymbolAddress((void**)&wkh, g_wkh);
    cudaGetSymbolAddress((void**)&wvh, g_wvh);
    cudaGetSymbolAddress((void**)&woh, g_woh);
    cudaGetSymbolAddress((void**)&aoh, g_aoh);

    cudaFuncSetAttribute(gemm_f16<true>,  cudaFuncAttributeMaxDynamicSharedMemorySize, GEMM_SMEM_BYTES);
    cudaFuncSetAttribute(gemm_f16<false>, cudaFuncAttributeMaxDynamicSharedMemorySize, GEMM_SMEM_BYTES);
    cudaFuncSetAttribute(flash_ws, cudaFuncAttributeMaxDynamicSharedMemorySize, FWS_SMEM);

    // fp32 -> fp16 converts
    {
        int n4x = MROWS*DMODEL/4;
        int n4w = DMODEL*DMODEL/4;
        f32_to_f16<<<(n4x+255)/256, 256>>>(x, xh, n4x);
        dim3 wgrid((n4w+255)/256, 4);
        w_to_f16<<<wgrid, 256>>>(wq, wk, wv, wo, wqh, wkh, wvh, woh, n4w);
    }

    // QKV projection with fused RoPE + fp16 epilogue
    dim3 qkv_grid(DMODEL/128, MROWS/128, 3);
    gemm_f16<true><<<qkv_grid, 256, GEMM_SMEM_BYTES>>>(xh, wqh, wkh, wvh,
                                                       nullptr, qh, kh, vh);

    // warp-specialized flash attention
    dim3 fgrid(SEQ/FBR, BATCH*HEADS);   // (32, 32)
    flash_ws<<<fgrid, 256, FWS_SMEM>>>(qh, kh, vh, aoh);

    // output projection (fp32 out)
    dim3 wo_grid(DMODEL/128, MROWS/128, 1);
    gemm_f16<false><<<wo_grid, 256, GEMM_SMEM_BYTES>>>(aoh, woh, nullptr, nullptr,
                                                       out, nullptr, nullptr, nullptr);
}